// round 3
// baseline (speedup 1.0000x reference)
#include <cuda_runtime.h>

#define NN 50000
#define NE 800000
#define NF 64
#define TPB 256
#define EPT 8
#define NE8 (NE / EPT)                     // 100000 edge-octets
#define EB  ((NE8 + TPB - 1) / TPB)        // 391 edge blocks
#define NB  ((NN + TPB - 1) / TPB)         // 196 node blocks
#define WB  (NN / (TPB / 32))              // 6250 warp-per-node blocks (exact)

// Scratch (__device__ globals, zero at module load; deg re-zeroed each call by H3).
__device__ __align__(16) float  g_deg[NN];
__device__ __align__(16) float2 g_p[NN];      // (dinv, y0) packed for 1-load gathers
__device__ __align__(16) float  g_sn[NN];     // self-loop norm = 1/(deg+1)
__device__ __align__(16) float  g_norm[NE];   // per-edge norm (written by H1)
__device__ __align__(16) float  g_y1[NN];
__device__ __align__(16) float  g_y2[NN];

// K1: (a) p[i].y = x[i,:]·W (warp per node)   (b) deg histogram, 8 edges/thread.
__global__ void k1(const float* __restrict__ x, const float* __restrict__ W,
                   const int* __restrict__ col) {
    if (blockIdx.x < WB) {
        __shared__ float sW[NF];
        if (threadIdx.x < NF) sW[threadIdx.x] = W[threadIdx.x];
        __syncthreads();
        int gw   = (blockIdx.x * TPB + threadIdx.x) >> 5;   // exact: WB*8 == NN
        int lane = threadIdx.x & 31;
        float2 v = ((const float2*)(x + (size_t)gw * NF))[lane];
        float s = fmaf(v.x, sW[2 * lane], v.y * sW[2 * lane + 1]);
        #pragma unroll
        for (int o = 16; o; o >>= 1) s += __shfl_xor_sync(0xffffffffu, s, o);
        if (lane == 0) g_p[gw].y = s;
    } else {
        int i = (blockIdx.x - WB) * TPB + threadIdx.x;
        if (i >= NE8) return;
        int4 c0 = ((const int4*)col)[2 * i];
        int4 c1 = ((const int4*)col)[2 * i + 1];
        atomicAdd(&g_deg[c0.x], 1.0f); atomicAdd(&g_deg[c0.y], 1.0f);
        atomicAdd(&g_deg[c0.z], 1.0f); atomicAdd(&g_deg[c0.w], 1.0f);
        atomicAdd(&g_deg[c1.x], 1.0f); atomicAdd(&g_deg[c1.y], 1.0f);
        atomicAdd(&g_deg[c1.z], 1.0f); atomicAdd(&g_deg[c1.w], 1.0f);
    }
}

// K2': node-only: dinv, self-norm, zero y1.
__global__ void k2() {
    int i = blockIdx.x * TPB + threadIdx.x;
    if (i >= NN) return;
    float d = g_deg[i] + 1.0f;      // +1 = self-loop
    g_p[i].x = rsqrtf(d);
    g_sn[i]  = 1.0f / d;
    g_y1[i]  = 0.0f;
}

// H1: fused norm-compute + hop1 (y0 -> y1), writes g_norm; node part: self edge + zero y2.
__global__ void h1(const int* __restrict__ row, const int* __restrict__ col) {
    if (blockIdx.x < EB) {
        int i = blockIdx.x * TPB + threadIdx.x;
        if (i >= NE8) return;
        int4 r0 = ((const int4*)row)[2 * i], r1 = ((const int4*)row)[2 * i + 1];
        int4 c0 = ((const int4*)col)[2 * i], c1 = ((const int4*)col)[2 * i + 1];
        int rr[8] = {r0.x, r0.y, r0.z, r0.w, r1.x, r1.y, r1.z, r1.w};
        int cc[8] = {c0.x, c0.y, c0.z, c0.w, c1.x, c1.y, c1.z, c1.w};
        float2 pr[8], pc[8];
        #pragma unroll
        for (int k = 0; k < 8; k++) pr[k] = g_p[rr[k]];
        #pragma unroll
        for (int k = 0; k < 8; k++) pc[k] = g_p[cc[k]];
        float nm[8];
        #pragma unroll
        for (int k = 0; k < 8; k++) nm[k] = pr[k].x * pc[k].x;
        ((float4*)g_norm)[2 * i]     = make_float4(nm[0], nm[1], nm[2], nm[3]);
        ((float4*)g_norm)[2 * i + 1] = make_float4(nm[4], nm[5], nm[6], nm[7]);
        #pragma unroll
        for (int k = 0; k < 8; k++) atomicAdd(&g_y1[cc[k]], nm[k] * pr[k].y);
    } else {
        int i = (blockIdx.x - EB) * TPB + threadIdx.x;
        if (i >= NN) return;
        atomicAdd(&g_y1[i], g_sn[i] * g_p[i].y);   // self edge
        g_y2[i] = 0.0f;
    }
}

// Generic hop (uses precomputed norm); node part: self edge + one fused aux store.
__global__ void hop(const float* __restrict__ yin, float* __restrict__ yout,
                    const int* __restrict__ row, const int* __restrict__ col,
                    float* __restrict__ aux, const float* __restrict__ bptr) {
    if (blockIdx.x < EB) {
        int i = blockIdx.x * TPB + threadIdx.x;
        if (i >= NE8) return;
        int4 r0 = ((const int4*)row)[2 * i], r1 = ((const int4*)row)[2 * i + 1];
        int4 c0 = ((const int4*)col)[2 * i], c1 = ((const int4*)col)[2 * i + 1];
        float4 n0 = ((const float4*)g_norm)[2 * i];
        float4 n1 = ((const float4*)g_norm)[2 * i + 1];
        int rr[8] = {r0.x, r0.y, r0.z, r0.w, r1.x, r1.y, r1.z, r1.w};
        int cc[8] = {c0.x, c0.y, c0.z, c0.w, c1.x, c1.y, c1.z, c1.w};
        float nm[8] = {n0.x, n0.y, n0.z, n0.w, n1.x, n1.y, n1.z, n1.w};
        float yv[8];
        #pragma unroll
        for (int k = 0; k < 8; k++) yv[k] = __ldg(&yin[rr[k]]);
        #pragma unroll
        for (int k = 0; k < 8; k++) atomicAdd(&yout[cc[k]], nm[k] * yv[k]);
    } else {
        int i = (blockIdx.x - EB) * TPB + threadIdx.x;
        if (i >= NN) return;
        atomicAdd(&yout[i], g_sn[i] * __ldg(&yin[i]));   // self edge
        aux[i] = bptr ? bptr[0] : 0.0f;
    }
}

extern "C" void kernel_launch(void* const* d_in, const int* in_sizes, int n_in,
                              void* d_out, int out_size) {
    const float* x  = (const float*)d_in[0];   // [NN, NF]
    const int*   ei = (const int*)d_in[1];     // [2, NE]
    const float* W  = (const float*)d_in[2];   // [1, NF]
    const float* b  = (const float*)d_in[3];   // [1]
    float* out = (float*)d_out;                // [NN]

    const int* row = ei;        // sources
    const int* col = ei + NE;   // destinations

    float *y1, *y2, *deg;
    cudaGetSymbolAddress((void**)&y1, g_y1);
    cudaGetSymbolAddress((void**)&y2, g_y2);
    cudaGetSymbolAddress((void**)&deg, g_deg);

    k1 <<<WB + EB, TPB>>>(x, W, col);            // dot -> p.y ; deg histogram
    k2 <<<NB, TPB>>>();                          // dinv/selfnorm/zero-y1 (node only)
    h1 <<<EB + NB, TPB>>>(row, col);             // hop1 fused with norm precompute; zero y2
    hop<<<EB + NB, TPB>>>(y1, y2, row, col, out, b);        // hop2 ; out = b
    hop<<<EB + NB, TPB>>>(y2, out, row, col, deg, nullptr); // hop3 ; deg = 0 for next call
}

// round 4
// speedup vs baseline: 1.1539x; 1.1539x over previous
#include <cuda_runtime.h>

#define NN 50000
#define NE 800000
#define NF 64
#define TPB 256
#define NE4 (NE / 4)                       // 200000 edge-quads
#define EB  ((NE4 + TPB - 1) / TPB)        // 782 edge blocks (4 edges/thread)
#define NB  ((NN + TPB - 1) / TPB)         // 196 node blocks
#define WB  (NN / (TPB / 32))              // 6250 warp-per-node blocks (exact)

// Scratch (__device__ globals; zero at load; deg re-zeroed by k6 each call).
__device__ __align__(16) float  g_deg[NN];
__device__ __align__(16) float2 g_T0[NN];   // (y0_dot, dinv)
__device__ __align__(16) float2 g_T1[NN];   // (acc,   1/deg~)
__device__ __align__(16) float2 g_T2[NN];   // (acc,   1/deg~)
__device__ __align__(16) float2 g_T3[NN];   // (acc,   unused)

// K1: (a) T0[i].x = x[i,:]·W (warp/node)   (b) degree histogram over col.
__global__ void k1(const float* __restrict__ x, const float* __restrict__ W,
                   const int* __restrict__ col) {
    if (blockIdx.x < WB) {
        __shared__ float sW[NF];
        if (threadIdx.x < NF) sW[threadIdx.x] = W[threadIdx.x];
        __syncthreads();
        int gw   = (blockIdx.x * TPB + threadIdx.x) >> 5;   // exact coverage
        int lane = threadIdx.x & 31;
        float2 v = ((const float2*)(x + (size_t)gw * NF))[lane];
        float s = fmaf(v.x, sW[2 * lane], v.y * sW[2 * lane + 1]);
        #pragma unroll
        for (int o = 16; o; o >>= 1) s += __shfl_xor_sync(0xffffffffu, s, o);
        if (lane == 0) g_T0[gw].x = s;
    } else {
        int i = (blockIdx.x - WB) * TPB + threadIdx.x;
        if (i >= NE4) return;
        int4 c = ((const int4*)col)[i];
        atomicAdd(&g_deg[c.x], 1.0f); atomicAdd(&g_deg[c.y], 1.0f);
        atomicAdd(&g_deg[c.z], 1.0f); atomicAdd(&g_deg[c.w], 1.0f);
    }
}

// K2: node-only scale fills + accumulator zeroing.
__global__ void k2() {
    int i = blockIdx.x * TPB + threadIdx.x;
    if (i >= NN) return;
    float d   = g_deg[i] + 1.0f;     // +1 = self-loop
    float di2 = 1.0f / d;
    g_T0[i].y = rsqrtf(d);           // D^{-1/2} applied at hop-1 gather
    g_T1[i] = make_float2(0.0f, di2);
    g_T2[i] = make_float2(0.0f, di2);
    g_T3[i].x = 0.0f;
}

// Uniform hop: Tout[c].x += Tin[r].x * Tin[r].y  (edge part, 4 edges/thread)
//              + self loop in spare node blocks.
__global__ void hop(const float2* __restrict__ Tin, float2* __restrict__ Tout,
                    const int* __restrict__ row, const int* __restrict__ col) {
    if (blockIdx.x < EB) {
        int i = blockIdx.x * TPB + threadIdx.x;
        if (i >= NE4) return;
        int4 r = ((const int4*)row)[i];
        int4 c = ((const int4*)col)[i];
        float2 a0 = Tin[r.x], a1 = Tin[r.y], a2 = Tin[r.z], a3 = Tin[r.w];
        atomicAdd(&Tout[c.x].x, a0.x * a0.y);
        atomicAdd(&Tout[c.y].x, a1.x * a1.y);
        atomicAdd(&Tout[c.z].x, a2.x * a2.y);
        atomicAdd(&Tout[c.w].x, a3.x * a3.y);
    } else {
        int i = (blockIdx.x - EB) * TPB + threadIdx.x;
        if (i >= NN) return;
        float2 a = Tin[i];
        atomicAdd(&Tout[i].x, a.x * a.y);     // self edge
    }
}

// K6: final scaling + bias; re-zero deg for the next replay.
__global__ void k6(float* __restrict__ out, const float* __restrict__ b) {
    int i = blockIdx.x * TPB + threadIdx.x;
    if (i >= NN) return;
    float d = g_deg[i] + 1.0f;
    out[i] = rsqrtf(d) * g_T3[i].x + b[0];
    g_deg[i] = 0.0f;
}

extern "C" void kernel_launch(void* const* d_in, const int* in_sizes, int n_in,
                              void* d_out, int out_size) {
    const float* x  = (const float*)d_in[0];   // [NN, NF]
    const int*   ei = (const int*)d_in[1];     // [2, NE]
    const float* W  = (const float*)d_in[2];   // [1, NF]
    const float* b  = (const float*)d_in[3];   // [1]
    float* out = (float*)d_out;                // [NN]

    const int* row = ei;        // sources
    const int* col = ei + NE;   // destinations

    float2 *T0, *T1, *T2, *T3;
    cudaGetSymbolAddress((void**)&T0, g_T0);
    cudaGetSymbolAddress((void**)&T1, g_T1);
    cudaGetSymbolAddress((void**)&T2, g_T2);
    cudaGetSymbolAddress((void**)&T3, g_T3);

    k1 <<<WB + EB, TPB>>>(x, W, col);        // dot + degree histogram
    k2 <<<NB, TPB>>>();                      // scales + zero accumulators
    hop<<<EB + NB, TPB>>>(T0, T1, row, col); // t1 = A~ (D^-1/2 y0)
    hop<<<EB + NB, TPB>>>(T1, T2, row, col); // t2 = A~ (D^-1 t1)
    hop<<<EB + NB, TPB>>>(T2, T3, row, col); // t3 = A~ (D^-1 t2)
    k6 <<<NB, TPB>>>(out, b);                // out = D^-1/2 t3 + b ; deg=0
}

// round 5
// speedup vs baseline: 1.1985x; 1.0386x over previous
#include <cuda_runtime.h>

#define NN 50000
#define NE 800000
#define NF 64
#define TPB 256
#define NE2 (NE / 2)                       // 400000 edge-pairs
#define EB  ((NE2 + TPB - 1) / TPB)        // 1563 edge blocks (2 edges/thread)
#define NB  ((NN + TPB - 1) / TPB)         // 196 node blocks
#define HWB (NN * 16 / TPB)                // 3125 half-warp-per-node blocks (exact)

// Scratch (__device__ globals; zero at load; deg re-zeroed by k6 each call).
__device__ __align__(16) float  g_deg[NN];
__device__ __align__(16) float2 g_T0[NN];   // (y0_dot, dinv)
__device__ __align__(16) float2 g_T1[NN];   // (acc, 1/deg~)
__device__ __align__(16) float2 g_T2[NN];   // (acc, 1/deg~)
__device__ __align__(16) float2 g_T3[NN];   // (acc, unused)

// K1: (a) T0[i].x = x[i,:]·W  — half-warp (16 lanes) per node, float4 loads.
//     (b) degree histogram over col — 2 edges/thread.
__global__ void k1(const float* __restrict__ x, const float* __restrict__ W,
                   const int* __restrict__ col) {
    if (blockIdx.x < HWB) {
        __shared__ float4 sW[NF / 4];
        if (threadIdx.x < NF / 4) sW[threadIdx.x] = ((const float4*)W)[threadIdx.x];
        __syncthreads();
        int t  = blockIdx.x * TPB + threadIdx.x;
        int gw = t >> 4;                 // node (exact coverage: HWB*16 == NN)
        int l  = t & 15;
        float4 v = ((const float4*)(x + (size_t)gw * NF))[l];
        float4 w = sW[l];
        float s = fmaf(v.x, w.x, fmaf(v.y, w.y, fmaf(v.z, w.z, v.w * w.w)));
        #pragma unroll
        for (int o = 8; o; o >>= 1) s += __shfl_xor_sync(0xffffffffu, s, o);
        if (l == 0) g_T0[gw].x = s;
    } else {
        int i = (blockIdx.x - HWB) * TPB + threadIdx.x;
        if (i >= NE2) return;
        int2 c = ((const int2*)col)[i];
        atomicAdd(&g_deg[c.x], 1.0f);
        atomicAdd(&g_deg[c.y], 1.0f);
    }
}

// K2: node-only scale fills + accumulator zeroing.
__global__ void k2() {
    int i = blockIdx.x * TPB + threadIdx.x;
    if (i >= NN) return;
    float d   = g_deg[i] + 1.0f;     // +1 = self-loop
    float di2 = 1.0f / d;
    g_T0[i].y = rsqrtf(d);           // D^{-1/2} applied at hop-1 gather
    g_T1[i] = make_float2(0.0f, di2);
    g_T2[i] = make_float2(0.0f, di2);
    g_T3[i].x = 0.0f;
}

// Uniform hop: Tout[c].x += Tin[r].x * Tin[r].y  (2 edges/thread)
//              + self loop in spare node blocks.
__global__ void hop(const float2* __restrict__ Tin, float2* __restrict__ Tout,
                    const int* __restrict__ row, const int* __restrict__ col) {
    if (blockIdx.x < EB) {
        int i = blockIdx.x * TPB + threadIdx.x;
        if (i >= NE2) return;
        int2 r = ((const int2*)row)[i];
        int2 c = ((const int2*)col)[i];
        float2 a0 = Tin[r.x];
        float2 a1 = Tin[r.y];
        atomicAdd(&Tout[c.x].x, a0.x * a0.y);
        atomicAdd(&Tout[c.y].x, a1.x * a1.y);
    } else {
        int i = (blockIdx.x - EB) * TPB + threadIdx.x;
        if (i >= NN) return;
        float2 a = Tin[i];
        atomicAdd(&Tout[i].x, a.x * a.y);     // self edge
    }
}

// K6: final scaling + bias; re-zero deg for the next replay.
__global__ void k6(float* __restrict__ out, const float* __restrict__ b) {
    int i = blockIdx.x * TPB + threadIdx.x;
    if (i >= NN) return;
    float d = g_deg[i] + 1.0f;
    out[i] = rsqrtf(d) * g_T3[i].x + b[0];
    g_deg[i] = 0.0f;
}

extern "C" void kernel_launch(void* const* d_in, const int* in_sizes, int n_in,
                              void* d_out, int out_size) {
    const float* x  = (const float*)d_in[0];   // [NN, NF]
    const int*   ei = (const int*)d_in[1];     // [2, NE]
    const float* W  = (const float*)d_in[2];   // [1, NF]
    const float* b  = (const float*)d_in[3];   // [1]
    float* out = (float*)d_out;                // [NN]

    const int* row = ei;        // sources
    const int* col = ei + NE;   // destinations

    float2 *T0, *T1, *T2, *T3;
    cudaGetSymbolAddress((void**)&T0, g_T0);
    cudaGetSymbolAddress((void**)&T1, g_T1);
    cudaGetSymbolAddress((void**)&T2, g_T2);
    cudaGetSymbolAddress((void**)&T3, g_T3);

    k1 <<<HWB + EB, TPB>>>(x, W, col);       // dot + degree histogram
    k2 <<<NB, TPB>>>();                      // scales + zero accumulators
    hop<<<EB + NB, TPB>>>(T0, T1, row, col); // t1 = A~ (D^-1/2 y0)
    hop<<<EB + NB, TPB>>>(T1, T2, row, col); // t2 = A~ (D^-1 t1)
    hop<<<EB + NB, TPB>>>(T2, T3, row, col); // t3 = A~ (D^-1 t2)
    k6 <<<NB, TPB>>>(out, b);                // out = D^-1/2 t3 + b ; deg=0
}